// round 2
// baseline (speedup 1.0000x reference)
#include <cuda_runtime.h>
#include <stdint.h>

// CoarseMatching fused single-read design.
// conf [N, L, S] fp32, L = 4800, S = 4800.
// Outputs (concatenated fp32): mconf [N*L], mask_v [N*L], all_j_ids [N*L].
//
// Fused pass (one read of conf):
//   - per-column max accumulated in registers, flushed once/block via atomicMax
//     (positive floats: uint order == float order)
//   - per-row top-2 of packed key (bits(v)<<32 | (0xFFFFFFFF - s))
//     -> rowmax value + first two row-argmax tie positions
// Finalize (tiny): mutual-NN check of the <=2 candidates against colmax,
// border validity, THR. Rescans a row only on a >=3-way fp32 tie at the max
// where the first two candidates both fail (probability ~1e-9).

#define THR  0.2f
#define BRM  2
#define H0   60
#define W0   80
#define H1   60
#define W1   80
#define LSZ  (H0 * W0)   // 4800
#define SSZ  (H1 * W1)   // 4800
#define MAXN 16
#define RPB  16          // rows per block in fused pass
#define SLOTS 5          // 1200 float4 cols / 256 threads -> 5 slots (last partial)

__device__ unsigned int        g_colmax[MAXN * SSZ];
__device__ unsigned long long  g_rowrec[MAXN * LSZ * 2];

__global__ void init_colmax_kernel(int total) {
    int i = blockIdx.x * blockDim.x + threadIdx.x;
    if (i < total) g_colmax[i] = 0u;
}

__device__ __forceinline__ void top2_upd(unsigned long long& t1, unsigned long long& t2,
                                         float v, int s) {
    const unsigned long long key =
        ((unsigned long long)__float_as_uint(v) << 32) |
        (unsigned long long)(0xFFFFFFFFu - (unsigned)s);
    if (key > t1) { t2 = t1; t1 = key; }
    else if (key > t2) { t2 = key; }
}

__device__ __forceinline__ void top2_merge(unsigned long long& t1, unsigned long long& t2,
                                           unsigned long long o1, unsigned long long o2) {
    const unsigned long long lo = (t1 < o1) ? t1 : o1;
    if (o1 > t1) t1 = o1;
    if (o2 > t2) t2 = o2;
    if (lo > t2) t2 = lo;
}

__global__ __launch_bounds__(256) void fused_kernel(const float* __restrict__ conf) {
    const int tid    = threadIdx.x;
    const int groups = LSZ / RPB;                  // 300
    const int n      = blockIdx.x / groups;
    const int lbase  = (blockIdx.x % groups) * RPB;

    float4 cm[SLOTS];
    #pragma unroll
    for (int k = 0; k < SLOTS; ++k) cm[k] = make_float4(0.f, 0.f, 0.f, 0.f);

    __shared__ unsigned long long s1[8], s2[8];

    const float4* base = reinterpret_cast<const float4*>(
        conf + ((size_t)n * LSZ + (size_t)lbase) * SSZ);

    for (int r = 0; r < RPB; ++r) {
        const float4* row = base + (size_t)r * (SSZ / 4);
        unsigned long long t1 = 0ull, t2 = 0ull;

        #pragma unroll
        for (int k = 0; k < SLOTS; ++k) {
            const int i = tid + k * 256;
            if (k < SLOTS - 1 || tid < (SSZ / 4 - 4 * 256)) {   // i < 1200
                const float4 v = row[i];
                cm[k].x = fmaxf(cm[k].x, v.x);
                cm[k].y = fmaxf(cm[k].y, v.y);
                cm[k].z = fmaxf(cm[k].z, v.z);
                cm[k].w = fmaxf(cm[k].w, v.w);
                const int s = i * 4;
                top2_upd(t1, t2, v.x, s + 0);
                top2_upd(t1, t2, v.y, s + 1);
                top2_upd(t1, t2, v.z, s + 2);
                top2_upd(t1, t2, v.w, s + 3);
            }
        }

        #pragma unroll
        for (int off = 16; off; off >>= 1) {
            const unsigned long long o1 = __shfl_down_sync(0xFFFFFFFFu, t1, off);
            const unsigned long long o2 = __shfl_down_sync(0xFFFFFFFFu, t2, off);
            top2_merge(t1, t2, o1, o2);
        }
        const int w = tid >> 5;
        if ((tid & 31) == 0) { s1[w] = t1; s2[w] = t2; }
        __syncthreads();
        if (tid == 0) {
            #pragma unroll
            for (int w2 = 1; w2 < 8; ++w2) top2_merge(t1, t2, s1[w2], s2[w2]);
            const size_t rec = ((size_t)n * LSZ + (size_t)(lbase + r)) * 2;
            g_rowrec[rec]     = t1;
            g_rowrec[rec + 1] = t2;
        }
        __syncthreads();
    }

    // flush per-block column max (one atomic per owned column)
    unsigned int* cmg = g_colmax + (size_t)n * SSZ;
    #pragma unroll
    for (int k = 0; k < SLOTS; ++k) {
        const int i = tid + k * 256;
        if (k < SLOTS - 1 || tid < (SSZ / 4 - 4 * 256)) {
            atomicMax(cmg + i * 4 + 0, __float_as_uint(cm[k].x));
            atomicMax(cmg + i * 4 + 1, __float_as_uint(cm[k].y));
            atomicMax(cmg + i * 4 + 2, __float_as_uint(cm[k].z));
            atomicMax(cmg + i * 4 + 3, __float_as_uint(cm[k].w));
        }
    }
}

__device__ __forceinline__ bool cand_ok(int n, unsigned rm, int j) {
    const int sr = j / W1, sc = j % W1;
    if (sr < BRM || sr >= H1 - BRM || sc < BRM || sc >= W1 - BRM) return false;
    return g_colmax[(size_t)n * SSZ + j] == rm;
}

__global__ __launch_bounds__(256) void finalize_kernel(const float* __restrict__ conf,
                                                       float* __restrict__ out, int N) {
    const int idx = blockIdx.x * blockDim.x + threadIdx.x;
    const int NL  = N * LSZ;
    if (idx >= NL) return;
    const int n = idx / LSZ, l = idx % LSZ;
    const int lr = l / W0, lc = l % W0;
    const bool v0 = (lr >= BRM) && (lr < H0 - BRM) && (lc >= BRM) && (lc < W0 - BRM);

    float mconf = 0.f, mv = 0.f;
    unsigned j = 0u;
    if (v0) {
        const unsigned long long t1 = g_rowrec[(size_t)idx * 2];
        const unsigned long long t2 = g_rowrec[(size_t)idx * 2 + 1];
        const unsigned rm = (unsigned)(t1 >> 32);
        const float rmf = __uint_as_float(rm);
        if (rmf > THR) {
            bool matched = false;
            const unsigned j1 = 0xFFFFFFFFu - (unsigned)(t1 & 0xFFFFFFFFull);
            if (cand_ok(n, rm, (int)j1)) { matched = true; j = j1; }
            else if ((unsigned)(t2 >> 32) == rm) {
                const unsigned j2 = 0xFFFFFFFFu - (unsigned)(t2 & 0xFFFFFFFFull);
                if (cand_ok(n, rm, (int)j2)) { matched = true; j = j2; }
                else {
                    // >=3-way tie at rowmax with first two failing: exact rescan
                    const float* row = conf + (size_t)idx * SSZ;
                    for (int s = 0; s < SSZ; ++s) {
                        if (__float_as_uint(row[s]) == rm && cand_ok(n, rm, s)) {
                            matched = true; j = (unsigned)s; break;
                        }
                    }
                }
            }
            if (matched) { mconf = rmf; mv = 1.f; }
        }
    }
    out[idx]          = mconf;
    out[NL + idx]     = mv;
    out[2 * NL + idx] = (float)j;
}

extern "C" void kernel_launch(void* const* d_in, const int* in_sizes, int n_in,
                              void* d_out, int out_size) {
    const float* conf = (const float*)d_in[0];
    const long long total = (long long)in_sizes[0];
    int N = (int)(total / ((long long)LSZ * (long long)SSZ));
    if (N < 1) N = 1;
    if (N > MAXN) N = MAXN;

    init_colmax_kernel<<<(N * SSZ + 255) / 256, 256>>>(N * SSZ);

    const int groups = LSZ / RPB;                  // 300
    fused_kernel<<<N * groups, 256>>>(conf);

    finalize_kernel<<<(N * LSZ + 255) / 256, 256>>>(conf, (float*)d_out, N);
}

// round 3
// speedup vs baseline: 3.1634x; 3.1634x over previous
#include <cuda_runtime.h>
#include <stdint.h>

// CoarseMatching, 2-pass (known-good structure), minimized per-element work.
// conf [N, L, S] fp32, L = 4800, S = 4800.
// Outputs (concatenated fp32): mconf [N*L], mask_v [N*L], all_j_ids [N*L].
//
// Pass 1 (colmax): full read, per-column max via atomicMax on float bits.
// Pass 2 (match):  per row: rowmax via plain fmaxf chains; candidate key
//   k2 = max over {s : bits(v)==colmax[s](poisoned for border) && v>THR}
//        of (bits(v)<<32 | (0xFFFFFFFF - s))
//   match iff top32(k2) == bits(rowmax); j = 0xFFFFFFFF - low32(k2).

#define THR  0.2f
#define BRM  2
#define H0   60
#define W0   80
#define H1   60
#define W1   80
#define LSZ  (H0 * W0)   // 4800
#define SSZ  (H1 * W1)   // 4800
#define MAXN 16
#define RPB  8
#define SLOTS 5          // ceil(1200 float4 / 256 threads)

__device__ unsigned int g_colmax[MAXN * SSZ];

__global__ void init_colmax_kernel(int total) {
    int i = blockIdx.x * blockDim.x + threadIdx.x;
    if (i < total) g_colmax[i] = 0u;
}

__global__ __launch_bounds__(256) void colmax_kernel(const float* __restrict__ conf) {
    const int n  = blockIdx.z;
    const int i4 = blockIdx.x * blockDim.x + threadIdx.x;
    if (i4 >= SSZ / 4) return;
    const int l0 = blockIdx.y * 100;

    const float4* p = reinterpret_cast<const float4*>(
        conf + ((size_t)n * LSZ + (size_t)l0) * SSZ) + i4;

    float4 m = make_float4(0.f, 0.f, 0.f, 0.f);
    #pragma unroll 5
    for (int t = 0; t < 100; ++t) {
        const float4 v = __ldcs(p);
        m.x = fmaxf(m.x, v.x);
        m.y = fmaxf(m.y, v.y);
        m.z = fmaxf(m.z, v.z);
        m.w = fmaxf(m.w, v.w);
        p += SSZ / 4;
    }
    unsigned int* cm = g_colmax + (size_t)n * SSZ + (size_t)i4 * 4;
    atomicMax(cm + 0, __float_as_uint(m.x));
    atomicMax(cm + 1, __float_as_uint(m.y));
    atomicMax(cm + 2, __float_as_uint(m.z));
    atomicMax(cm + 3, __float_as_uint(m.w));
}

__global__ __launch_bounds__(256) void match_kernel(const float* __restrict__ conf,
                                                    float* __restrict__ out, int N) {
    __shared__ float              s_m[RPB * 8];
    __shared__ unsigned long long s_k[RPB * 8];

    const int tid    = threadIdx.x;
    const int groups = LSZ / RPB;                  // 600
    const int n      = blockIdx.x / groups;
    const int lbase  = (blockIdx.x % groups) * RPB;
    const int NL     = N * LSZ;
    const int w      = tid >> 5, lane = tid & 31;

    // Column max -> registers, with border-invalid columns poisoned to
    // 0xFFFFFFFF (no conf bit pattern < 1.0f can equal it). L2-resident.
    uint4 cm[SLOTS];
    #pragma unroll
    for (int k = 0; k < SLOTS; ++k) {
        const int i = tid + k * 256;
        if (k < SLOTS - 1 || tid < (SSZ / 4 - 4 * 256)) {
            uint4 c = *reinterpret_cast<const uint4*>(g_colmax + (size_t)n * SSZ + (size_t)i * 4);
            const int s0 = i * 4;
            const int sr = s0 / W1, sc = s0 % W1;      // 4 | W1 -> same row for all 4
            const bool rok = (sr >= BRM) && (sr < H1 - BRM);
            if (!(rok && sc + 0 >= BRM && sc + 0 < W1 - BRM)) c.x = 0xFFFFFFFFu;
            if (!(rok && sc + 1 >= BRM && sc + 1 < W1 - BRM)) c.y = 0xFFFFFFFFu;
            if (!(rok && sc + 2 >= BRM && sc + 2 < W1 - BRM)) c.z = 0xFFFFFFFFu;
            if (!(rok && sc + 3 >= BRM && sc + 3 < W1 - BRM)) c.w = 0xFFFFFFFFu;
            cm[k] = c;
        }
    }

    #pragma unroll 1
    for (int r = 0; r < RPB; ++r) {
        const int l  = lbase + r;
        const int lr = l / W0, lc = l % W0;
        if (lr < BRM || lr >= H0 - BRM || lc < BRM || lc >= W0 - BRM) continue; // uniform

        const float4* row = reinterpret_cast<const float4*>(
            conf + ((size_t)n * LSZ + (size_t)l) * SSZ);

        float mx = 0.f, my = 0.f, mz = 0.f, mw = 0.f;
        unsigned long long k2 = 0ull;

        #pragma unroll
        for (int k = 0; k < SLOTS; ++k) {
            const int i = tid + k * 256;
            if (k < SLOTS - 1 || tid < (SSZ / 4 - 4 * 256)) {
                const float4 v = __ldcs(&row[i]);
                mx = fmaxf(mx, v.x);
                my = fmaxf(my, v.y);
                mz = fmaxf(mz, v.z);
                mw = fmaxf(mw, v.w);
                // rare candidate: bits match the (poisoned) column max AND > THR
                const unsigned fx = __float_as_uint(v.x);
                const unsigned fy = __float_as_uint(v.y);
                const unsigned fz = __float_as_uint(v.z);
                const unsigned fw = __float_as_uint(v.w);
                if (fx == cm[k].x && v.x > THR) {
                    const unsigned long long key = ((unsigned long long)fx << 32)
                        | (unsigned long long)(0xFFFFFFFFu - (unsigned)(i * 4 + 0));
                    if (key > k2) k2 = key;
                }
                if (fy == cm[k].y && v.y > THR) {
                    const unsigned long long key = ((unsigned long long)fy << 32)
                        | (unsigned long long)(0xFFFFFFFFu - (unsigned)(i * 4 + 1));
                    if (key > k2) k2 = key;
                }
                if (fz == cm[k].z && v.z > THR) {
                    const unsigned long long key = ((unsigned long long)fz << 32)
                        | (unsigned long long)(0xFFFFFFFFu - (unsigned)(i * 4 + 2));
                    if (key > k2) k2 = key;
                }
                if (fw == cm[k].w && v.w > THR) {
                    const unsigned long long key = ((unsigned long long)fw << 32)
                        | (unsigned long long)(0xFFFFFFFFu - (unsigned)(i * 4 + 3));
                    if (key > k2) k2 = key;
                }
            }
        }

        float m = fmaxf(fmaxf(mx, my), fmaxf(mz, mw));
        #pragma unroll
        for (int off = 16; off; off >>= 1) {
            m = fmaxf(m, __shfl_down_sync(0xFFFFFFFFu, m, off));
            const unsigned long long o2 = __shfl_down_sync(0xFFFFFFFFu, k2, off);
            if (o2 > k2) k2 = o2;
        }
        if (lane == 0) { s_m[r * 8 + w] = m; s_k[r * 8 + w] = k2; }
    }

    __syncthreads();

    if (tid < RPB) {
        const int l  = lbase + tid;
        const int o  = n * LSZ + l;
        const int lr = l / W0, lc = l % W0;
        const bool v0 = (lr >= BRM) && (lr < H0 - BRM) && (lc >= BRM) && (lc < W0 - BRM);

        float mconf = 0.f, mv = 0.f;
        unsigned j = 0u;
        if (v0) {
            float m = s_m[tid * 8];
            unsigned long long k2 = s_k[tid * 8];
            #pragma unroll
            for (int w2 = 1; w2 < 8; ++w2) {
                m = fmaxf(m, s_m[tid * 8 + w2]);
                if (s_k[tid * 8 + w2] > k2) k2 = s_k[tid * 8 + w2];
            }
            const unsigned rm = __float_as_uint(m);
            if (k2 != 0ull && (unsigned)(k2 >> 32) == rm) {
                mconf = m; mv = 1.f;
                j = 0xFFFFFFFFu - (unsigned)(k2 & 0xFFFFFFFFull);
            }
        }
        out[o]          = mconf;
        out[NL + o]     = mv;
        out[2 * NL + o] = (float)j;
    }
}

extern "C" void kernel_launch(void* const* d_in, const int* in_sizes, int n_in,
                              void* d_out, int out_size) {
    const float* conf = (const float*)d_in[0];
    const long long total = (long long)in_sizes[0];
    int N = (int)(total / ((long long)LSZ * (long long)SSZ));
    if (N < 1) N = 1;
    if (N > MAXN) N = MAXN;

    init_colmax_kernel<<<(N * SSZ + 255) / 256, 256>>>(N * SSZ);

    dim3 g1((SSZ / 4 + 255) / 256, LSZ / 100, N);   // (5, 48, N)
    colmax_kernel<<<g1, 256>>>(conf);

    match_kernel<<<N * (LSZ / RPB), 256>>>(conf, (float*)d_out, N);
}

// round 4
// speedup vs baseline: 3.3267x; 1.0516x over previous
#include <cuda_runtime.h>
#include <stdint.h>

// CoarseMatching, 2-pass, minimal per-element work.
// conf [N, L, S] fp32, L = 4800, S = 4800.
// Outputs (concatenated fp32): mconf [N*L], mask_v [N*L], all_j_ids [N*L].
//
// Pass 1 (colmax): full read, per-column max via atomicMax on float bits.
// Pass 2 (match): colmax staged in registers with border-invalid AND
//   (<= THR) columns poisoned to 0xFFFFFFFF. Per element: rowmax fmax chain
//   + single bits==colmax compare; rare branch tracks (best, first-j).
//   match iff best == rowmax.

#define THR  0.2f
#define BRM  2
#define H0   60
#define W0   80
#define H1   60
#define W1   80
#define LSZ  (H0 * W0)   // 4800
#define SSZ  (H1 * W1)   // 4800
#define MAXN 16
#define RPB  16
#define SLOTS 5          // ceil(1200 float4 / 256 threads)

__device__ unsigned int g_colmax[MAXN * SSZ];

__global__ __launch_bounds__(256) void colmax_kernel(const float* __restrict__ conf) {
    const int n  = blockIdx.z;
    const int i4 = blockIdx.x * blockDim.x + threadIdx.x;
    if (i4 >= SSZ / 4) return;
    const int l0 = blockIdx.y * 100;

    const float4* p = reinterpret_cast<const float4*>(
        conf + ((size_t)n * LSZ + (size_t)l0) * SSZ) + i4;

    float4 m = make_float4(0.f, 0.f, 0.f, 0.f);
    #pragma unroll 5
    for (int t = 0; t < 100; ++t) {
        const float4 v = __ldcs(p);
        m.x = fmaxf(m.x, v.x);
        m.y = fmaxf(m.y, v.y);
        m.z = fmaxf(m.z, v.z);
        m.w = fmaxf(m.w, v.w);
        p += SSZ / 4;
    }
    unsigned int* cm = g_colmax + (size_t)n * SSZ + (size_t)i4 * 4;
    atomicMax(cm + 0, __float_as_uint(m.x));
    atomicMax(cm + 1, __float_as_uint(m.y));
    atomicMax(cm + 2, __float_as_uint(m.z));
    atomicMax(cm + 3, __float_as_uint(m.w));
}

__global__ __launch_bounds__(256) void match_kernel(const float* __restrict__ conf,
                                                    float* __restrict__ out, int N) {
    __shared__ float s_m [RPB * 8];
    __shared__ float s_bv[RPB * 8];
    __shared__ int   s_bj[RPB * 8];

    const int tid    = threadIdx.x;
    const int groups = LSZ / RPB;                  // 300
    const int n      = blockIdx.x / groups;
    const int lbase  = (blockIdx.x % groups) * RPB;
    const int NL     = N * LSZ;
    const int w      = tid >> 5, lane = tid & 31;

    // 16 | 80 -> all RPB rows of this block share the same lr.
    const int lr = lbase / W0;
    const bool lr_ok = (lr >= BRM) && (lr < H0 - BRM);

    if (lr_ok) {
        // Stage column max into registers. Poison border-invalid columns AND
        // columns whose max <= THR with 0xFFFFFFFF (unreachable by conf bits).
        uint4 cm[SLOTS];
        #pragma unroll
        for (int k = 0; k < SLOTS; ++k) {
            const int i = tid + k * 256;
            if (k < SLOTS - 1 || tid < (SSZ / 4 - 4 * 256)) {
                uint4 c = *reinterpret_cast<const uint4*>(
                    g_colmax + (size_t)n * SSZ + (size_t)i * 4);
                const int s0 = i * 4;
                const int sr = s0 / W1, sc = s0 % W1;     // 4 | W1 -> same sr for all 4
                const bool rok = (sr >= BRM) && (sr < H1 - BRM);
                if (!(rok && sc + 0 >= BRM && sc + 0 < W1 - BRM) || __uint_as_float(c.x) <= THR) c.x = 0xFFFFFFFFu;
                if (!(rok && sc + 1 >= BRM && sc + 1 < W1 - BRM) || __uint_as_float(c.y) <= THR) c.y = 0xFFFFFFFFu;
                if (!(rok && sc + 2 >= BRM && sc + 2 < W1 - BRM) || __uint_as_float(c.z) <= THR) c.z = 0xFFFFFFFFu;
                if (!(rok && sc + 3 >= BRM && sc + 3 < W1 - BRM) || __uint_as_float(c.w) <= THR) c.w = 0xFFFFFFFFu;
                cm[k] = c;
            }
        }

        #pragma unroll 1
        for (int r = 0; r < RPB; ++r) {
            const int l  = lbase + r;
            const int lc = l % W0;
            if (lc < BRM || lc >= W0 - BRM) continue;   // uniform across block

            const float4* row = reinterpret_cast<const float4*>(
                conf + ((size_t)n * LSZ + (size_t)l) * SSZ);

            float mx = 0.f, my = 0.f, mz = 0.f, mw = 0.f;
            float bv = 0.f;
            int   bj = 0;

            #pragma unroll
            for (int k = 0; k < SLOTS; ++k) {
                const int i = tid + k * 256;
                if (k < SLOTS - 1 || tid < (SSZ / 4 - 4 * 256)) {
                    const float4 v = __ldcs(&row[i]);
                    mx = fmaxf(mx, v.x);
                    my = fmaxf(my, v.y);
                    mz = fmaxf(mz, v.z);
                    mw = fmaxf(mw, v.w);
                    const bool c0 = (__float_as_uint(v.x) == cm[k].x);
                    const bool c1 = (__float_as_uint(v.y) == cm[k].y);
                    const bool c2 = (__float_as_uint(v.z) == cm[k].z);
                    const bool c3 = (__float_as_uint(v.w) == cm[k].w);
                    if (c0 | c1 | c2 | c3) {            // rare (~1 per column)
                        const int s0 = i * 4;
                        if (c0 && v.x > bv) { bv = v.x; bj = s0 + 0; }
                        if (c1 && v.y > bv) { bv = v.y; bj = s0 + 1; }
                        if (c2 && v.z > bv) { bv = v.z; bj = s0 + 2; }
                        if (c3 && v.w > bv) { bv = v.w; bj = s0 + 3; }
                    }
                }
            }

            float m = fmaxf(fmaxf(mx, my), fmaxf(mz, mw));
            #pragma unroll
            for (int off = 16; off; off >>= 1) {
                m = fmaxf(m, __shfl_down_sync(0xFFFFFFFFu, m, off));
                const float ov = __shfl_down_sync(0xFFFFFFFFu, bv, off);
                const int   oj = __shfl_down_sync(0xFFFFFFFFu, bj, off);
                if (ov > bv || (ov == bv && oj < bj)) { bv = ov; bj = oj; }
            }
            if (lane == 0) {
                s_m [r * 8 + w] = m;
                s_bv[r * 8 + w] = bv;
                s_bj[r * 8 + w] = bj;
            }
        }
    }

    __syncthreads();

    if (tid < RPB) {
        const int l = lbase + tid;
        const int o = n * LSZ + l;
        const int lc = l % W0;
        const bool v0 = lr_ok && (lc >= BRM) && (lc < W0 - BRM);

        float mconf = 0.f, mv = 0.f;
        int j = 0;
        if (v0) {
            float m  = s_m [tid * 8];
            float bv = s_bv[tid * 8];
            int   bj = s_bj[tid * 8];
            #pragma unroll
            for (int w2 = 1; w2 < 8; ++w2) {
                m = fmaxf(m, s_m[tid * 8 + w2]);
                const float ov = s_bv[tid * 8 + w2];
                const int   oj = s_bj[tid * 8 + w2];
                if (ov > bv || (ov == bv && oj < bj)) { bv = ov; bj = oj; }
            }
            if (bv > 0.f && bv == m) { mconf = m; mv = 1.f; j = bj; }
        }
        out[o]          = mconf;
        out[NL + o]     = mv;
        out[2 * NL + o] = (float)j;
    }
}

extern "C" void kernel_launch(void* const* d_in, const int* in_sizes, int n_in,
                              void* d_out, int out_size) {
    const float* conf = (const float*)d_in[0];
    const long long total = (long long)in_sizes[0];
    int N = (int)(total / ((long long)LSZ * (long long)SSZ));
    if (N < 1) N = 1;
    if (N > MAXN) N = MAXN;

    // zero colmax scratch via memset node (replaces init kernel)
    void* cm_ptr = nullptr;
    cudaGetSymbolAddress(&cm_ptr, g_colmax);
    cudaMemsetAsync(cm_ptr, 0, (size_t)N * SSZ * sizeof(unsigned int));

    dim3 g1((SSZ / 4 + 255) / 256, LSZ / 100, N);   // (5, 48, N)
    colmax_kernel<<<g1, 256>>>(conf);

    match_kernel<<<N * (LSZ / RPB), 256>>>(conf, (float*)d_out, N);
}

// round 5
// speedup vs baseline: 3.4233x; 1.0290x over previous
#include <cuda_runtime.h>
#include <stdint.h>

// CoarseMatching, 2-pass.
// conf [N, L, S] fp32, L = 4800, S = 4800.
// Outputs (concatenated fp32): mconf [N*L], mask_v [N*L], all_j_ids [N*L].
//
// Pass 1 (colmax): full read, per-column max via atomicMax on float bits.
// Pass 2 (match): colmax staged in SMEM with border-invalid and (<= THR)
//   columns poisoned to 0xFFFFFFFF. Per element: rowmax fmax chain + one
//   bits==colmax compare; rare branch tracks (best, first-j).
//   match iff best == rowmax.

#define THR  0.2f
#define BRM  2
#define H0   60
#define W0   80
#define H1   60
#define W1   80
#define LSZ  (H0 * W0)   // 4800
#define SSZ  (H1 * W1)   // 4800
#define MAXN 16
#define RPB  16
#define SLOTS 5          // ceil(1200 float4 / 256 threads)

__device__ unsigned int g_colmax[MAXN * SSZ];

__global__ __launch_bounds__(256) void colmax_kernel(const float* __restrict__ conf) {
    const int n  = blockIdx.z;
    const int i4 = blockIdx.x * blockDim.x + threadIdx.x;
    if (i4 >= SSZ / 4) return;
    const int l0 = blockIdx.y * 100;

    const float4* p = reinterpret_cast<const float4*>(
        conf + ((size_t)n * LSZ + (size_t)l0) * SSZ) + i4;

    float4 m = make_float4(0.f, 0.f, 0.f, 0.f);
    #pragma unroll 5
    for (int t = 0; t < 100; ++t) {
        const float4 v = *p;
        m.x = fmaxf(m.x, v.x);
        m.y = fmaxf(m.y, v.y);
        m.z = fmaxf(m.z, v.z);
        m.w = fmaxf(m.w, v.w);
        p += SSZ / 4;
    }
    unsigned int* cm = g_colmax + (size_t)n * SSZ + (size_t)i4 * 4;
    atomicMax(cm + 0, __float_as_uint(m.x));
    atomicMax(cm + 1, __float_as_uint(m.y));
    atomicMax(cm + 2, __float_as_uint(m.z));
    atomicMax(cm + 3, __float_as_uint(m.w));
}

__global__ __launch_bounds__(256, 6) void match_kernel(const float* __restrict__ conf,
                                                       float* __restrict__ out, int N) {
    __shared__ unsigned s_cm[SSZ];                  // 19.2 KB poisoned colmax
    __shared__ float s_m [RPB * 8];
    __shared__ float s_bv[RPB * 8];
    __shared__ int   s_bj[RPB * 8];

    const int tid    = threadIdx.x;
    const int groups = LSZ / RPB;                   // 300
    const int n      = blockIdx.x / groups;
    const int lbase  = (blockIdx.x % groups) * RPB;
    const int NL     = N * LSZ;
    const int w      = tid >> 5, lane = tid & 31;

    // 16 | 80 -> all RPB rows of this block share the same lr.
    const int lr = lbase / W0;
    const bool lr_ok = (lr >= BRM) && (lr < H0 - BRM);

    if (lr_ok) {
        // Stage colmax into SMEM; poison border-invalid columns and columns
        // whose max <= THR with 0xFFFFFFFF (unreachable by any conf bits).
        #pragma unroll
        for (int k = 0; k < SLOTS; ++k) {
            const int i = tid + k * 256;
            if (k < SLOTS - 1 || tid < (SSZ / 4 - 4 * 256)) {
                uint4 c = *reinterpret_cast<const uint4*>(
                    g_colmax + (size_t)n * SSZ + (size_t)i * 4);
                const int s0 = i * 4;
                const int sr = s0 / W1, sc = s0 % W1;      // 4 | W1: same sr for all 4
                const bool rok = (sr >= BRM) && (sr < H1 - BRM);
                if (!(rok && sc + 0 >= BRM && sc + 0 < W1 - BRM) || __uint_as_float(c.x) <= THR) c.x = 0xFFFFFFFFu;
                if (!(rok && sc + 1 >= BRM && sc + 1 < W1 - BRM) || __uint_as_float(c.y) <= THR) c.y = 0xFFFFFFFFu;
                if (!(rok && sc + 2 >= BRM && sc + 2 < W1 - BRM) || __uint_as_float(c.z) <= THR) c.z = 0xFFFFFFFFu;
                if (!(rok && sc + 3 >= BRM && sc + 3 < W1 - BRM) || __uint_as_float(c.w) <= THR) c.w = 0xFFFFFFFFu;
                *reinterpret_cast<uint4*>(&s_cm[s0]) = c;
            }
        }
        __syncthreads();

        const uint4* cm4 = reinterpret_cast<const uint4*>(s_cm);

        #pragma unroll 1
        for (int r = 0; r < RPB; ++r) {
            const int l  = lbase + r;
            const int lc = l % W0;
            if (lc < BRM || lc >= W0 - BRM) continue;   // uniform across block

            const float4* row = reinterpret_cast<const float4*>(
                conf + ((size_t)n * LSZ + (size_t)l) * SSZ);

            float mx = 0.f, my = 0.f, mz = 0.f, mw = 0.f;
            float bv = 0.f;
            int   bj = 0;

            #pragma unroll
            for (int k = 0; k < SLOTS; ++k) {
                const int i = tid + k * 256;
                if (k < SLOTS - 1 || tid < (SSZ / 4 - 4 * 256)) {
                    const float4 v = __ldcs(&row[i]);
                    const uint4  c = cm4[i];
                    mx = fmaxf(mx, v.x);
                    my = fmaxf(my, v.y);
                    mz = fmaxf(mz, v.z);
                    mw = fmaxf(mw, v.w);
                    const bool c0 = (__float_as_uint(v.x) == c.x);
                    const bool c1 = (__float_as_uint(v.y) == c.y);
                    const bool c2 = (__float_as_uint(v.z) == c.z);
                    const bool c3 = (__float_as_uint(v.w) == c.w);
                    if (c0 | c1 | c2 | c3) {            // rare (~1 per column)
                        const int s0 = i * 4;
                        if (c0 && v.x > bv) { bv = v.x; bj = s0 + 0; }
                        if (c1 && v.y > bv) { bv = v.y; bj = s0 + 1; }
                        if (c2 && v.z > bv) { bv = v.z; bj = s0 + 2; }
                        if (c3 && v.w > bv) { bv = v.w; bj = s0 + 3; }
                    }
                }
            }

            float m = fmaxf(fmaxf(mx, my), fmaxf(mz, mw));
            #pragma unroll
            for (int off = 16; off; off >>= 1) {
                m = fmaxf(m, __shfl_down_sync(0xFFFFFFFFu, m, off));
                const float ov = __shfl_down_sync(0xFFFFFFFFu, bv, off);
                const int   oj = __shfl_down_sync(0xFFFFFFFFu, bj, off);
                if (ov > bv || (ov == bv && oj < bj)) { bv = ov; bj = oj; }
            }
            if (lane == 0) {
                s_m [r * 8 + w] = m;
                s_bv[r * 8 + w] = bv;
                s_bj[r * 8 + w] = bj;
            }
        }
    }

    __syncthreads();

    if (tid < RPB) {
        const int l = lbase + tid;
        const int o = n * LSZ + l;
        const int lc = l % W0;
        const bool v0 = lr_ok && (lc >= BRM) && (lc < W0 - BRM);

        float mconf = 0.f, mv = 0.f;
        int j = 0;
        if (v0) {
            float m  = s_m [tid * 8];
            float bv = s_bv[tid * 8];
            int   bj = s_bj[tid * 8];
            #pragma unroll
            for (int w2 = 1; w2 < 8; ++w2) {
                m = fmaxf(m, s_m[tid * 8 + w2]);
                const float ov = s_bv[tid * 8 + w2];
                const int   oj = s_bj[tid * 8 + w2];
                if (ov > bv || (ov == bv && oj < bj)) { bv = ov; bj = oj; }
            }
            if (bv > 0.f && bv == m) { mconf = m; mv = 1.f; j = bj; }
        }
        out[o]          = mconf;
        out[NL + o]     = mv;
        out[2 * NL + o] = (float)j;
    }
}

extern "C" void kernel_launch(void* const* d_in, const int* in_sizes, int n_in,
                              void* d_out, int out_size) {
    const float* conf = (const float*)d_in[0];
    const long long total = (long long)in_sizes[0];
    int N = (int)(total / ((long long)LSZ * (long long)SSZ));
    if (N < 1) N = 1;
    if (N > MAXN) N = MAXN;

    void* cm_ptr = nullptr;
    cudaGetSymbolAddress(&cm_ptr, g_colmax);
    cudaMemsetAsync(cm_ptr, 0, (size_t)N * SSZ * sizeof(unsigned int));

    dim3 g1((SSZ / 4 + 255) / 256, LSZ / 100, N);   // (5, 48, N)
    colmax_kernel<<<g1, 256>>>(conf);

    match_kernel<<<N * (LSZ / RPB), 256>>>(conf, (float*)d_out, N);
}